// round 13
// baseline (speedup 1.0000x reference)
#include <cuda_runtime.h>
#include <cuda_bf16.h>

#define NMAX 10
#define LP1  8
#define NZ   80
#define THR  0.0625f
#define CAP  (1u << 21)

__device__ unsigned int g_ctr;
__device__ unsigned int g_list[CAP];   // packed (i << 4) | n
__device__ float        g_zp[NZ];      // 1 / z_{n,l}^{l+1}  (double-precision build)

// ---------- K0: reset counter + build z-power reciprocal table ----------
__global__ void rb_init_kernel(const float* __restrict__ zeros)
{
    const int t = threadIdx.x;
    if (t == 0) g_ctr = 0;
    if (t < NZ) {
        const int l = t & 7;
        const double z = (double)zeros[t];
        double p = 1.0;
        for (int m = 0; m <= l; ++m) p *= z;
        g_zp[t] = (float)(1.0 / p);
    }
}

// ---------- K1: division-free fast kernel + in-register compaction ----------
// j_l = q_l * (1/z^{l+1}) * (1/t^{l+1}),  t = rv*0.2
//   q_0 = s,  q_1 = s - c*x,  q_k = (2k-1) q_{k-1} - x^2 q_{k-2}
// MUFU per element: sin + cos only (rcp amortized to 1 per thread).
__global__ void __launch_bounds__(320, 6)
rb_fast_kernel(const float* __restrict__ r,
               const float* __restrict__ zeros,   // [NMAX, LP1]
               float* __restrict__ out,           // [N, LP1, NMAX]
               int nEdges)
{
    const int tid = threadIdx.x;            // 320 = 32 edges * 10 n
    const int i   = blockIdx.x * 32 + tid / NMAX;
    if (i >= nEdges) return;
    const int n   = tid - (tid / NMAX) * NMAX;

    const float rv   = __ldg(&r[i]);
    const float rv02 = rv * 0.2f;
    float tinv;
    asm("rcp.approx.f32 %0, %1;" : "=f"(tinv) : "f"(rv02));

    const float4 za = __ldg((const float4*)(zeros + n * LP1));
    const float4 zb = __ldg((const float4*)(zeros + n * LP1) + 1);
    const float z[8] = {za.x, za.y, za.z, za.w, zb.x, zb.y, zb.z, zb.w};

    float* o = out + (size_t)i * NZ + n;

    float tpow = tinv;                       // tinv^{l+1}, running product
    #pragma unroll
    for (int l = 0; l < LP1; ++l) {
        const float x  = z[l] * rv02;
        float s, c;
        asm("sin.approx.f32 %0, %1;" : "=f"(s) : "f"(x));
        asm("cos.approx.f32 %0, %1;" : "=f"(c) : "f"(x));

        float q = s;                         // q_0
        if (l >= 1) {
            const float xx = x * x;
            float qm1 = q;
            q = fmaf(-c, x, s);              // q_1
            #pragma unroll
            for (int k = 2; k <= l; ++k) {
                const float qn = fmaf((float)(2 * k - 1), q, -(xx * qm1));
                qm1 = q; q = qn;
            }
        }
        const float zp = __ldg(&g_zp[n * LP1 + l]);
        o[l * NMAX] = q * (zp * tpow);
        tpow *= tinv;
    }

    // compaction: exact-bit gate on l=0 (minimal x for this (i,n))
    const float x0e = __fmul_rn(__fmul_rn(z[0], rv), 0.2f);
    if (x0e < THR) {
        const unsigned mask   = __activemask();
        const int      lane   = tid & 31;
        const int      leader = __ffs(mask) - 1;
        const int      prefix = __popc(mask & ((1u << lane) - 1));
        unsigned base = 0;
        if (lane == leader) base = atomicAdd(&g_ctr, (unsigned)__popc(mask));
        base = __shfl_sync(mask, base, leader);
        const unsigned slot = base + prefix;
        if (slot < CAP)
            g_list[slot] = ((unsigned)i << 4) | (unsigned)n;
    }
}

// ---------- exact path (bit-validated rounds 4-12) ----------
__device__ __noinline__ float jl_exact(int l, float x)
{
    const double xd = (double)x;
    const double x2 = xd * xd;
    double sp = fma(x2,  1.0/6227020800.0, -1.0/39916800.0);
    sp = fma(x2, sp,  1.0/362880.0);
    sp = fma(x2, sp, -1.0/5040.0);
    sp = fma(x2, sp,  1.0/120.0);
    sp = fma(x2, sp, -1.0/6.0);
    const float s = __double2float_rn(fma(xd * x2, sp, xd));
    double cp = fma(x2, -1.0/87178291200.0, 1.0/479001600.0);
    cp = fma(x2, cp, -1.0/3628800.0);
    cp = fma(x2, cp,  1.0/40320.0);
    cp = fma(x2, cp, -1.0/720.0);
    cp = fma(x2, cp,  1.0/24.0);
    cp = fma(x2, cp, -0.5);
    const float c = __double2float_rn(fma(x2, cp, 1.0));

    float jm1 = __fdiv_rn(s, x);                                   // j0
    if (l == 0) return jm1;
    const float xx = __fmul_rn(x, x);
    float j = __fsub_rn(__fdiv_rn(s, xx), __fdiv_rn(c, x));        // j1
    #pragma unroll
    for (int k = 2; k <= 7; ++k) {
        if (k > l) break;
        float jn = __fsub_rn(__fmul_rn(__fdiv_rn((float)(2 * k - 1), x), j), jm1);
        jm1 = j; j = jn;
    }
    return j;
}

// ---------- K2: parallel fixup, ~1 exact eval per thread ----------
__global__ void __launch_bounds__(256)
rb_fixup_kernel(const float* __restrict__ r,
                const float* __restrict__ zeros,
                float* __restrict__ out)
{
    const unsigned count  = min(g_ctr, CAP);
    const unsigned items  = count * LP1;
    const unsigned stride = gridDim.x * blockDim.x;

    for (unsigned j = blockIdx.x * blockDim.x + threadIdx.x; j < items; j += stride) {
        const unsigned p = g_list[j >> 3];
        const int l = (int)(j & 7u);
        const int i = (int)(p >> 4);
        const int n = (int)(p & 15u);
        const float rv = __ldg(&r[i]);
        const float z  = __ldg(&zeros[n * LP1 + l]);
        const float x  = __fmul_rn(__fmul_rn(z, rv), 0.2f);
        if (x < THR)
            out[(size_t)i * NZ + l * NMAX + n] = jl_exact(l, x);
    }
}

extern "C" void kernel_launch(void* const* d_in, const int* in_sizes, int n_in,
                              void* d_out, int out_size)
{
    const float* r     = (const float*)d_in[0];
    const float* zeros = (const float*)d_in[1];
    float* out         = (float*)d_out;
    const int n = in_sizes[0];

    rb_init_kernel<<<1, 128>>>(zeros);
    rb_fast_kernel<<<(n + 31) / 32, 320>>>(r, zeros, out, n);
    rb_fixup_kernel<<<3700, 256>>>(r, zeros, out);
}

// round 14
// speedup vs baseline: 1.0987x; 1.0987x over previous
#include <cuda_runtime.h>
#include <cuda_bf16.h>

#define NMAX 10
#define LP1  8
#define NZ   80
#define THR  0.0625f
#define CAP  (1u << 21)
#define BSTR 84                    // padded floats per edge in smem buf

__device__ unsigned int g_ctr;
__device__ unsigned int g_list[CAP];   // packed (i << 4) | n

// ---------- K0: reset compaction counter ----------
__global__ void rb_init_kernel()
{
    if (threadIdx.x == 0) g_ctr = 0;
}

// ---------- K1: round-12 compute (3 MUFU, reg z) — ONLY change: smem-staged
// stores + coalesced flush. No early return (barrier); dead lanes clamped. ----------
__global__ void __launch_bounds__(320, 6)
rb_fast_kernel(const float* __restrict__ r,
               const float* __restrict__ zeros,   // [NMAX, LP1]
               float* __restrict__ out,           // [N, LP1, NMAX]
               int nEdges)
{
    __shared__ float buf[32 * BSTR];

    const int tid  = threadIdx.x;            // 320 = 32 edges * 10 n
    const int e    = tid / NMAX;
    const int n    = tid - e * NMAX;
    const int base = blockIdx.x * 32;
    const int i0   = base + e;
    const bool live = (i0 < nEdges);
    const int i    = live ? i0 : (nEdges - 1);

    const float rv   = __ldg(&r[i]);
    const float rv02 = rv * 0.2f;
    const float4 za = __ldg((const float4*)(zeros + n * LP1));
    const float4 zb = __ldg((const float4*)(zeros + n * LP1) + 1);
    const float z[8] = {za.x, za.y, za.z, za.w, zb.x, zb.y, zb.z, zb.w};

    float* o = buf + e * BSTR + n;

    #pragma unroll
    for (int l = 0; l < LP1; ++l) {
        const float x = z[l] * rv02;
        float s, c, u;
        asm("sin.approx.f32 %0, %1;" : "=f"(s) : "f"(x));
        asm("cos.approx.f32 %0, %1;" : "=f"(c) : "f"(x));
        asm("rcp.approx.f32 %0, %1;" : "=f"(u) : "f"(x));
        float jm1 = s * u;                       // j0
        float v = jm1;
        if (l >= 1) {
            float j = fmaf(jm1, u, -(c * u));    // j1
            #pragma unroll
            for (int k = 2; k <= l; ++k) {
                float jn = fmaf((float)(2 * k - 1) * u, j, -jm1);
                jm1 = j; j = jn;
            }
            v = j;
        }
        o[l * NMAX] = v;
    }

    // compaction: exact-bit gate on l=0 (minimal x for this (i,n))
    const float x0e = __fmul_rn(__fmul_rn(z[0], rv), 0.2f);
    if (live && x0e < THR) {
        const unsigned mask   = __activemask();
        const int      lane   = tid & 31;
        const int      leader = __ffs(mask) - 1;
        const int      prefix = __popc(mask & ((1u << lane) - 1));
        unsigned bslot = 0;
        if (lane == leader) bslot = atomicAdd(&g_ctr, (unsigned)__popc(mask));
        bslot = __shfl_sync(mask, bslot, leader);
        const unsigned slot = bslot + prefix;
        if (slot < CAP)
            g_list[slot] = ((unsigned)i0 << 4) | (unsigned)n;
    }

    __syncthreads();

    // coalesced flush: 32 edges * 20 float4 = 640 float4, 2 per thread
    float4* o4 = (float4*)(out + (size_t)base * NZ);
    #pragma unroll
    for (int k = 0; k < 2; ++k) {
        const int j4 = tid + k * 320;             // 0..639
        const int ee = j4 / 20;
        const int w  = j4 - ee * 20;
        if (base + ee < nEdges)
            o4[j4] = *((const float4*)(buf + ee * BSTR) + w);
    }
}

// ---------- exact path (bit-validated rounds 4-13) ----------
__device__ __noinline__ float jl_exact(int l, float x)
{
    const double xd = (double)x;
    const double x2 = xd * xd;
    double sp = fma(x2,  1.0/6227020800.0, -1.0/39916800.0);
    sp = fma(x2, sp,  1.0/362880.0);
    sp = fma(x2, sp, -1.0/5040.0);
    sp = fma(x2, sp,  1.0/120.0);
    sp = fma(x2, sp, -1.0/6.0);
    const float s = __double2float_rn(fma(xd * x2, sp, xd));
    double cp = fma(x2, -1.0/87178291200.0, 1.0/479001600.0);
    cp = fma(x2, cp, -1.0/3628800.0);
    cp = fma(x2, cp,  1.0/40320.0);
    cp = fma(x2, cp, -1.0/720.0);
    cp = fma(x2, cp,  1.0/24.0);
    cp = fma(x2, cp, -0.5);
    const float c = __double2float_rn(fma(x2, cp, 1.0));

    float jm1 = __fdiv_rn(s, x);                                   // j0
    if (l == 0) return jm1;
    const float xx = __fmul_rn(x, x);
    float j = __fsub_rn(__fdiv_rn(s, xx), __fdiv_rn(c, x));        // j1
    #pragma unroll
    for (int k = 2; k <= 7; ++k) {
        if (k > l) break;
        float jn = __fsub_rn(__fmul_rn(__fdiv_rn((float)(2 * k - 1), x), j), jm1);
        jm1 = j; j = jn;
    }
    return j;
}

// ---------- K2: parallel fixup, ~1 exact eval per thread ----------
__global__ void __launch_bounds__(256)
rb_fixup_kernel(const float* __restrict__ r,
                const float* __restrict__ zeros,
                float* __restrict__ out)
{
    const unsigned count  = min(g_ctr, CAP);
    const unsigned items  = count * LP1;
    const unsigned stride = gridDim.x * blockDim.x;

    for (unsigned j = blockIdx.x * blockDim.x + threadIdx.x; j < items; j += stride) {
        const unsigned p = g_list[j >> 3];
        const int l = (int)(j & 7u);
        const int i = (int)(p >> 4);
        const int n = (int)(p & 15u);
        const float rv = __ldg(&r[i]);
        const float z  = __ldg(&zeros[n * LP1 + l]);
        const float x  = __fmul_rn(__fmul_rn(z, rv), 0.2f);
        if (x < THR)
            out[(size_t)i * NZ + l * NMAX + n] = jl_exact(l, x);
    }
}

extern "C" void kernel_launch(void* const* d_in, const int* in_sizes, int n_in,
                              void* d_out, int out_size)
{
    const float* r     = (const float*)d_in[0];
    const float* zeros = (const float*)d_in[1];
    float* out         = (float*)d_out;
    const int n = in_sizes[0];

    rb_init_kernel<<<1, 32>>>();
    rb_fast_kernel<<<(n + 31) / 32, 320>>>(r, zeros, out, n);
    rb_fixup_kernel<<<3700, 256>>>(r, zeros, out);
}